// round 11
// baseline (speedup 1.0000x reference)
#include <cuda_runtime.h>
#include <cuda_fp16.h>
#include <math.h>
#include <stdint.h>

#define BATCH 2
#define SEQ   2048
#define DIM   2048
#define KVDIM 512
#define NH    16
#define NKV   4
#define HD    128

// Scratch (__device__ globals: allocation-free rule)
__device__ __half g_Xh[BATCH * SEQ * DIM];
__device__ __half g_Wqh[DIM * DIM];
__device__ __half g_Wkh[KVDIM * DIM];
__device__ __half g_Wvh[KVDIM * DIM];
__device__ __half g_Woh[DIM * DIM];
__device__ __half g_Qh[BATCH * SEQ * DIM];
__device__ __half g_Kh[BATCH * SEQ * KVDIM];
__device__ __half g_Vh[BATCH * SEQ * KVDIM];
__device__ __half g_AOh[BATCH * SEQ * DIM];

__device__ __forceinline__ uint32_t h2u(__half2 h) {
    uint32_t u;
    memcpy(&u, &h, 4);
    return u;
}

__device__ __forceinline__ uint32_t smem_u32(const void* p) {
    return (uint32_t)__cvta_generic_to_shared(p);
}

__device__ __forceinline__ void mma16(float* d, const uint32_t* a, const uint32_t* b) {
    asm volatile(
        "mma.sync.aligned.m16n8k16.row.col.f32.f16.f16.f32 "
        "{%0,%1,%2,%3}, {%4,%5,%6,%7}, {%8,%9}, {%0,%1,%2,%3};"
        : "+f"(d[0]), "+f"(d[1]), "+f"(d[2]), "+f"(d[3])
        : "r"(a[0]), "r"(a[1]), "r"(a[2]), "r"(a[3]), "r"(b[0]), "r"(b[1]));
}

__device__ __forceinline__ void ldsm4(uint32_t* r, uint32_t saddr) {
    asm volatile(
        "ldmatrix.sync.aligned.m8n8.x4.shared.b16 {%0,%1,%2,%3}, [%4];"
        : "=r"(r[0]), "=r"(r[1]), "=r"(r[2]), "=r"(r[3]) : "r"(saddr));
}
__device__ __forceinline__ void ldsm4t(uint32_t* r, uint32_t saddr) {
    asm volatile(
        "ldmatrix.sync.aligned.m8n8.x4.trans.shared.b16 {%0,%1,%2,%3}, [%4];"
        : "=r"(r[0]), "=r"(r[1]), "=r"(r[2]), "=r"(r[3]) : "r"(saddr));
}

__device__ __forceinline__ void cp16(void* smem_dst, const void* gmem_src) {
    uint32_t sa = (uint32_t)__cvta_generic_to_shared(smem_dst);
    asm volatile("cp.async.cg.shared.global [%0], [%1], 16;\n" ::"r"(sa), "l"(gmem_src));
}
#define CP_COMMIT() asm volatile("cp.async.commit_group;\n" ::)
#define CP_WAIT(N) asm volatile("cp.async.wait_group %0;\n" ::"n"(N))

// ---------------------------------------------------------------------------
// One flattened launch converting all 5 fp32 tensors to fp16 (no idle blocks)
// ---------------------------------------------------------------------------
__global__ void to_half_all(const float2* s0, __half2* d0, int n0,
                            const float2* s1, __half2* d1, int n1,
                            const float2* s2, __half2* d2, int n2,
                            const float2* s3, __half2* d3, int n3,
                            const float2* s4, __half2* d4, int n4) {
    int i = blockIdx.x * blockDim.x + threadIdx.x;
    if (i < n0) { float2 v = s0[i]; d0[i] = __floats2half2_rn(v.x, v.y); return; }
    i -= n0;
    if (i < n1) { float2 v = s1[i]; d1[i] = __floats2half2_rn(v.x, v.y); return; }
    i -= n1;
    if (i < n2) { float2 v = s2[i]; d2[i] = __floats2half2_rn(v.x, v.y); return; }
    i -= n2;
    if (i < n3) { float2 v = s3[i]; d3[i] = __floats2half2_rn(v.x, v.y); return; }
    i -= n3;
    if (i < n4) { float2 v = s4[i]; d4[i] = __floats2half2_rn(v.x, v.y); }
}

// ---------------------------------------------------------------------------
// Shared GEMM body (fp16 mma + ldmatrix, 3-stage cp.async).
// Block 128x128, 8 warps (2Mx4N), warp 64x32, BK=32h.
// ---------------------------------------------------------------------------
#define HSTR2 20
#define HSTAGES 3
#define HSTAGE_U32 (128 * HSTR2)
#define HGEMM_SMEM (HSTAGES * 2 * HSTAGE_U32 * 4)  // 61440 B

template <bool HALF_OUT>
__device__ __forceinline__ void gemm_body(const __half* __restrict__ A,
                                          const __half* __restrict__ B,
                                          void* __restrict__ Cv, int N, int K,
                                          int mBase, int nBase, uint32_t* smp) {
    const uint32_t smb = smem_u32(smp);
    const int tid = threadIdx.x;
    const int lane = tid & 31;
    const int warp = tid >> 5;
    const int wm = warp >> 2;
    const int wn = warp & 3;
    const int gr = lane >> 2, tc = lane & 3;

    const int mat = lane >> 3;
    const int arow = (lane & 7) + ((mat & 1) << 3);
    const int acol = (mat >> 1) << 3;
    const int brow = (lane & 7) + ((mat >> 1) << 3);
    const int bcol = (mat & 1) << 3;

    float acc[4][4][4];
#pragma unroll
    for (int i = 0; i < 4; i++)
#pragma unroll
        for (int j = 0; j < 4; j++)
#pragma unroll
            for (int r = 0; r < 4; r++) acc[i][j][r] = 0.f;

    const int nK = K / 32;

#define GSTAGE(kt, s)                                                          \
    do {                                                                       \
        _Pragma("unroll") for (int i = 0; i < 2; i++) {                        \
            int c = tid + i * 256;                                             \
            int r = c >> 2, ch = c & 3;                                        \
            cp16(&smp[((s)*128 + r) * HSTR2 + ch * 4],                         \
                 A + (size_t)(mBase + r) * K + (kt)*32 + ch * 8);              \
            cp16(&smp[(HSTAGES * 128 + (s)*128 + r) * HSTR2 + ch * 4],         \
                 B + (size_t)(nBase + r) * K + (kt)*32 + ch * 8);              \
        }                                                                      \
    } while (0)

    GSTAGE(0, 0);
    CP_COMMIT();
    GSTAGE(1, 1);
    CP_COMMIT();

    for (int kt = 0; kt < nK; kt++) {
        CP_WAIT(1);
        __syncthreads();
        int nxt = kt + 2;
        if (nxt < nK) GSTAGE(nxt, nxt % HSTAGES);
        CP_COMMIT();

        const uint32_t Aoff = smb + (uint32_t)(kt % HSTAGES) * (HSTAGE_U32 * 4);
        const uint32_t Boff = Aoff + HSTAGES * (HSTAGE_U32 * 4);
#pragma unroll
        for (int ks = 0; ks < 2; ks++) {
            const int k0h = ks * 16;
            uint32_t af[4][4], bf0[4], bf1[4];
#pragma unroll
            for (int mt = 0; mt < 4; mt++)
                ldsm4(af[mt], Aoff + (wm * 64 + mt * 16 + arow) * 80 +
                                  (k0h + acol) * 2);
            ldsm4(bf0, Boff + (wn * 32 + brow) * 80 + (k0h + bcol) * 2);
            ldsm4(bf1, Boff + (wn * 32 + 16 + brow) * 80 + (k0h + bcol) * 2);
#pragma unroll
            for (int mt = 0; mt < 4; mt++) {
                mma16(acc[mt][0], af[mt], bf0 + 0);
                mma16(acc[mt][1], af[mt], bf0 + 2);
                mma16(acc[mt][2], af[mt], bf1 + 0);
                mma16(acc[mt][3], af[mt], bf1 + 2);
            }
        }
        __syncthreads();
    }
#undef GSTAGE

#pragma unroll
    for (int mt = 0; mt < 4; mt++) {
        int m0 = mBase + wm * 64 + mt * 16;
#pragma unroll
        for (int nt = 0; nt < 4; nt++) {
            int n0 = nBase + wn * 32 + nt * 8 + 2 * tc;
            if (HALF_OUT) {
                __half2* cp = (__half2*)((__half*)Cv + (size_t)(m0 + gr) * N + n0);
                __half2* cp2 = (__half2*)((__half*)Cv + (size_t)(m0 + gr + 8) * N + n0);
                *cp = __floats2half2_rn(acc[mt][nt][0], acc[mt][nt][1]);
                *cp2 = __floats2half2_rn(acc[mt][nt][2], acc[mt][nt][3]);
            } else {
                float* cp = (float*)Cv + (size_t)(m0 + gr) * N + n0;
                float* cp2 = (float*)Cv + (size_t)(m0 + gr + 8) * N + n0;
                cp[0] = acc[mt][nt][0];
                cp[1] = acc[mt][nt][1];
                cp2[0] = acc[mt][nt][2];
                cp2[1] = acc[mt][nt][3];
            }
        }
    }
}

// Merged Q/K/V projection: grid.x = 24 n-blocks (16 Q | 4 K | 4 V), grid.y = M/128
__global__ __launch_bounds__(256) void gemm_qkv(const __half* __restrict__ Xh,
                                                const __half* __restrict__ Wq,
                                                __half* __restrict__ Qd,
                                                const __half* __restrict__ Wk,
                                                __half* __restrict__ Kd,
                                                const __half* __restrict__ Wv,
                                                __half* __restrict__ Vd) {
    extern __shared__ uint32_t smp[];
    const int bx = blockIdx.x;
    const __half* B;
    __half* C;
    int N, nb;
    if (bx < 16) {
        B = Wq; C = Qd; N = DIM; nb = bx;
    } else if (bx < 20) {
        B = Wk; C = Kd; N = KVDIM; nb = bx - 16;
    } else {
        B = Wv; C = Vd; N = KVDIM; nb = bx - 20;
    }
    gemm_body<true>(Xh, B, C, N, DIM, blockIdx.y * 128, nb * 128, smp);
}

// O projection (fp32 out)
__global__ __launch_bounds__(256) void gemm_o(const __half* __restrict__ A,
                                              const __half* __restrict__ B,
                                              float* __restrict__ C) {
    extern __shared__ uint32_t smp[];
    gemm_body<false>(A, B, C, DIM, DIM, blockIdx.y * 128, blockIdx.x * 128, smp);
}

// ---------------------------------------------------------------------------
// Merged RoPE for Q and K (flattened index; Q gets 1/sqrt(128)*log2e folded)
// ---------------------------------------------------------------------------
__global__ void rope_both(__half* __restrict__ Qd, __half* __restrict__ Kd,
                          int qCount, float qscale) {
    int idx = blockIdx.x * blockDim.x + threadIdx.x;
    __half* X;
    int nCols, nHeads;
    float scale;
    if (idx < qCount) {
        X = Qd; nCols = DIM; nHeads = NH; scale = qscale;
    } else {
        idx -= qCount;
        X = Kd; nCols = KVDIM; nHeads = NKV; scale = 1.0f;
    }
    int i = idx & 63;
    int h = (idx >> 6) % nHeads;
    int row = idx / (64 * nHeads);
    int l = row & (SEQ - 1);

    float freq = expf(-(float)i * 0.14391156831212787f);
    float ang = (float)l * freq;
    float s, c;
    sincosf(ang, &s, &c);

    __half* p = X + (size_t)row * nCols + h * HD + i;
    float x1 = __half2float(p[0]);
    float x2 = __half2float(p[64]);
    p[0] = __float2half_rn((x1 * c - x2 * s) * scale);
    p[64] = __float2half_rn((x2 * c + x1 * s) * scale);
}

// ---------------------------------------------------------------------------
// Flash attention, fp16 mma + ldmatrix, cp.async pipelined, exp2 softmax.
// Q-tile pairing (i, 15-i): uniform 17 unit-tiles; 256 CTAs = one wave.
// smem: Qs[128][68], Ks[2][64][68], Vs[64][68] (b32 strides) = 87040 B.
// ---------------------------------------------------------------------------
#define AQS2 68
#define ATTN_SMEM ((128 * AQS2 + 2 * 64 * AQS2 + 64 * AQS2) * 4)

__global__ __launch_bounds__(256) void attn_h(const __half* __restrict__ Q,
                                              const __half* __restrict__ K,
                                              const __half* __restrict__ V,
                                              __half* __restrict__ O) {
    extern __shared__ uint32_t sm[];
    uint32_t* Qs = sm;                       // [128][68] b32
    uint32_t* Ks = Qs + 128 * AQS2;          // [2][64][68]
    uint32_t* Vs = Ks + 2 * 64 * AQS2;       // [64][68]

    const uint32_t Qaddr = smem_u32(Qs);
    const uint32_t Kaddr0 = smem_u32(Ks);
    const uint32_t Vaddr = smem_u32(Vs);

    const int tid = threadIdx.x, lane = tid & 31, warp = tid >> 5;
    const int gr = lane >> 2, tc = lane & 3;
    const int h = blockIdx.y, b = blockIdx.z;
    const int kh = h >> 2;
    const int nqt = gridDim.x * 2;  // 16 q-tiles total

    const int mat = lane >> 3;
    const int arow = (lane & 7) + ((mat & 1) << 3);
    const int acol = (mat >> 1) << 3;
    const int brow = (lane & 7) + ((mat >> 1) << 3);
    const int bcol = (mat & 1) << 3;

    const __half* Kbase = K + ((size_t)(b * SEQ)) * KVDIM + kh * HD;
    const __half* Vbase = V + ((size_t)(b * SEQ)) * KVDIM + kh * HD;
    const int q0 = warp * 16;

    for (int halfIdx = 0; halfIdx < 2; halfIdx++) {
        const int qTile = halfIdx ? (nqt - 1 - (int)blockIdx.x) : (int)blockIdx.x;
        const int qBase = qTile * 128;
        const __half* Qp = Q + ((size_t)(b * SEQ + qBase)) * DIM + h * HD;

        __syncthreads();

        // Prologue: stage Q + K(0)
        {
#pragma unroll
            for (int i = 0; i < 8; i++) {
                int c = tid + i * 256;
                int q = c >> 4;
                int ch = c & 15;
                cp16((char*)Qs + q * (AQS2 * 4) + ch * 16,
                     Qp + (size_t)q * DIM + ch * 8);
            }
#pragma unroll
            for (int i = 0; i < 4; i++) {
                int c = tid + i * 256;
                int key = c >> 4;
                int ch = c & 15;
                cp16((char*)Ks + key * (AQS2 * 4) + ch * 16,
                     Kbase + (size_t)key * KVDIM + ch * 8);
            }
            CP_COMMIT();
        }

        float m0r = -1e30f, m1r = -1e30f, l0 = 0.f, l1 = 0.f;
        float o[16][4];
#pragma unroll
        for (int i = 0; i < 16; i++)
#pragma unroll
            for (int j = 0; j < 4; j++) o[i][j] = 0.f;

        const int nT = 2 * qTile + 2;

        for (int t = 0; t < nT; t++) {
            const int buf = t & 1;
            CP_WAIT(0);
            __syncthreads();

            // Issue V(t)
            {
                const __half* Vp = Vbase + (size_t)(t * 64) * KVDIM;
#pragma unroll
                for (int i = 0; i < 4; i++) {
                    int c = tid + i * 256;
                    int key = c >> 4;
                    int ch = c & 15;
                    cp16((char*)Vs + key * (AQS2 * 4) + ch * 16,
                         Vp + (size_t)key * KVDIM + ch * 8);
                }
            }
            CP_COMMIT();
            // Issue K(t+1)
            if (t + 1 < nT) {
                const __half* Kp = Kbase + (size_t)((t + 1) * 64) * KVDIM;
                uint32_t* Kd = Ks + ((t + 1) & 1) * 64 * AQS2;
#pragma unroll
                for (int i = 0; i < 4; i++) {
                    int c = tid + i * 256;
                    int key = c >> 4;
                    int ch = c & 15;
                    cp16((char*)Kd + key * (AQS2 * 4) + ch * 16,
                         Kp + (size_t)key * KVDIM + ch * 8);
                }
            }
            CP_COMMIT();

            // S = Q*K^T (log2 domain)
            const uint32_t Kaddr = Kaddr0 + (uint32_t)buf * (64 * AQS2 * 4);
            float s[8][4];
#pragma unroll
            for (int nt = 0; nt < 8; nt++)
#pragma unroll
                for (int r = 0; r < 4; r++) s[nt][r] = 0.f;

#pragma unroll
            for (int dk = 0; dk < 8; dk++) {
                const int d0h = dk * 16;
                uint32_t aq[4];
                ldsm4(aq, Qaddr + (q0 + arow) * (AQS2 * 4) + (d0h + acol) * 2);
#pragma unroll
                for (int p = 0; p < 4; p++) {
                    uint32_t bk[4];
                    ldsm4(bk, Kaddr + (p * 16 + brow) * (AQS2 * 4) + (d0h + bcol) * 2);
                    mma16(s[2 * p], aq, bk + 0);
                    mma16(s[2 * p + 1], aq, bk + 2);
                }
            }

            // Causal mask
            if (t * 64 >= qBase) {
                int qrow = qBase + q0 + gr;
                int kcol = t * 64 + 2 * tc;
#pragma unroll
                for (int nt = 0; nt < 8; nt++) {
                    int kc = kcol + nt * 8;
                    if (kc > qrow) s[nt][0] = -1e30f;
                    if (kc + 1 > qrow) s[nt][1] = -1e30f;
                    if (kc > qrow + 8) s[nt][2] = -1e30f;
                    if (kc + 1 > qrow + 8) s[nt][3] = -1e30f;
                }
            }

            // Online softmax (exp2 domain)
            float rm0 = -1e30f, rm1 = -1e30f;
#pragma unroll
            for (int nt = 0; nt < 8; nt++) {
                rm0 = fmaxf(rm0, fmaxf(s[nt][0], s[nt][1]));
                rm1 = fmaxf(rm1, fmaxf(s[nt][2], s[nt][3]));
            }
            rm0 = fmaxf(rm0, __shfl_xor_sync(0xffffffffu, rm0, 1));
            rm0 = fmaxf(rm0, __shfl_xor_sync(0xffffffffu, rm0, 2));
            rm1 = fmaxf(rm1, __shfl_xor_sync(0xffffffffu, rm1, 1));
            rm1 = fmaxf(rm1, __shfl_xor_sync(0xffffffffu, rm1, 2));

            float mn0 = fmaxf(m0r, rm0), mn1 = fmaxf(m1r, rm1);
            float a0 = exp2f(m0r - mn0), a1 = exp2f(m1r - mn1);
            m0r = mn0;
            m1r = mn1;

            float rs0 = 0.f, rs1 = 0.f;
#pragma unroll
            for (int nt = 0; nt < 8; nt++) {
                s[nt][0] = exp2f(s[nt][0] - mn0);
                s[nt][1] = exp2f(s[nt][1] - mn0);
                s[nt][2] = exp2f(s[nt][2] - mn1);
                s[nt][3] = exp2f(s[nt][3] - mn1);
                rs0 += s[nt][0] + s[nt][1];
                rs1 += s[nt][2] + s[nt][3];
            }
            rs0 += __shfl_xor_sync(0xffffffffu, rs0, 1);
            rs0 += __shfl_xor_sync(0xffffffffu, rs0, 2);
            rs1 += __shfl_xor_sync(0xffffffffu, rs1, 1);
            rs1 += __shfl_xor_sync(0xffffffffu, rs1, 2);
            l0 = l0 * a0 + rs0;
            l1 = l1 * a1 + rs1;

#pragma unroll
            for (int ot = 0; ot < 16; ot++) {
                o[ot][0] *= a0;
                o[ot][1] *= a0;
                o[ot][2] *= a1;
                o[ot][3] *= a1;
            }

            // P fragments directly from S registers (C-frag == A-frag layout)
            uint32_t pf[4][4];
#pragma unroll
            for (int kk = 0; kk < 4; kk++) {
                pf[kk][0] = h2u(__floats2half2_rn(s[2 * kk][0], s[2 * kk][1]));
                pf[kk][1] = h2u(__floats2half2_rn(s[2 * kk][2], s[2 * kk][3]));
                pf[kk][2] = h2u(__floats2half2_rn(s[2 * kk + 1][0], s[2 * kk + 1][1]));
                pf[kk][3] = h2u(__floats2half2_rn(s[2 * kk + 1][2], s[2 * kk + 1][3]));
            }

            // V(t) must have landed (K(t+1) group still in flight)
            CP_WAIT(1);
            __syncthreads();

            // O += P * V : V frags via ldmatrix.trans
#pragma unroll
            for (int kk = 0; kk < 4; kk++) {
                const int k0h = kk * 16;
#pragma unroll
                for (int dp = 0; dp < 8; dp++) {
                    uint32_t bv[4];
                    ldsm4t(bv, Vaddr + (k0h + arow) * (AQS2 * 4) +
                                   (dp * 16 + acol) * 2);
                    mma16(o[2 * dp], pf[kk], bv + 0);
                    mma16(o[2 * dp + 1], pf[kk], bv + 2);
                }
            }
        }

        // Normalize + write half (feeds O-projection GEMM)
        float inv0 = 1.f / l0, inv1 = 1.f / l1;
        __half* Op = O + ((size_t)(b * SEQ + qBase + q0)) * DIM + h * HD;
#pragma unroll
        for (int ot = 0; ot < 16; ot++) {
            int d0 = ot * 8 + 2 * tc;
            *(__half2*)(Op + (size_t)gr * DIM + d0) =
                __floats2half2_rn(o[ot][0] * inv0, o[ot][1] * inv0);
            *(__half2*)(Op + (size_t)(gr + 8) * DIM + d0) =
                __floats2half2_rn(o[ot][2] * inv1, o[ot][3] * inv1);
        }
    }
}

// ---------------------------------------------------------------------------
extern "C" void kernel_launch(void* const* d_in, const int* in_sizes, int n_in,
                              void* d_out, int out_size) {
    const float* x = (const float*)d_in[0];
    const float* Wq = (const float*)d_in[1];
    const float* Wk = (const float*)d_in[2];
    const float* Wv = (const float*)d_in[3];
    const float* Wo = (const float*)d_in[4];
    float* out = (float*)d_out;

    __half *Xh, *Wqh, *Wkh, *Wvh, *Woh, *Qh, *Kh, *Vh, *AOh;
    cudaGetSymbolAddress((void**)&Xh, g_Xh);
    cudaGetSymbolAddress((void**)&Wqh, g_Wqh);
    cudaGetSymbolAddress((void**)&Wkh, g_Wkh);
    cudaGetSymbolAddress((void**)&Wvh, g_Wvh);
    cudaGetSymbolAddress((void**)&Woh, g_Woh);
    cudaGetSymbolAddress((void**)&Qh, g_Qh);
    cudaGetSymbolAddress((void**)&Kh, g_Kh);
    cudaGetSymbolAddress((void**)&Vh, g_Vh);
    cudaGetSymbolAddress((void**)&AOh, g_AOh);

    const int M = BATCH * SEQ;  // 4096

    // Single flattened conversion launch
    {
        int n0 = M * DIM / 2;        // x
        int n1 = DIM * DIM / 2;      // Wq
        int n2 = KVDIM * DIM / 2;    // Wk
        int n3 = KVDIM * DIM / 2;    // Wv
        int n4 = DIM * DIM / 2;      // Wo
        int total = n0 + n1 + n2 + n3 + n4;
        to_half_all<<<(total + 255) / 256, 256>>>(
            (const float2*)x, (__half2*)Xh, n0, (const float2*)Wq, (__half2*)Wqh,
            n1, (const float2*)Wk, (__half2*)Wkh, n2, (const float2*)Wv,
            (__half2*)Wvh, n3, (const float2*)Wo, (__half2*)Woh, n4);
    }

    cudaFuncSetAttribute(gemm_qkv, cudaFuncAttributeMaxDynamicSharedMemorySize,
                         HGEMM_SMEM);
    cudaFuncSetAttribute(gemm_o, cudaFuncAttributeMaxDynamicSharedMemorySize,
                         HGEMM_SMEM);

    // Q, K, V projections in one launch: 24 n-blocks x 32 m-blocks
    gemm_qkv<<<dim3(24, M / 128), 256, HGEMM_SMEM>>>(Xh, Wqh, Qh, Wkh, Kh, Wvh, Vh);

    // Merged RoPE (Q scale folds 1/sqrt(128)*log2e for exp2 softmax)
    {
        const float qscale = 0.08838834764831845f * 1.4426950408889634f;
        int qCount = BATCH * SEQ * NH * 64;
        int kCount = BATCH * SEQ * NKV * 64;
        rope_both<<<(qCount + kCount + 255) / 256, 256>>>(Qh, Kh, qCount, qscale);
    }

    cudaFuncSetAttribute(attn_h, cudaFuncAttributeMaxDynamicSharedMemorySize,
                         ATTN_SMEM);
    attn_h<<<dim3(SEQ / 256, NH, BATCH), 256, ATTN_SMEM>>>(Qh, Kh, Vh, AOh);

    gemm_o<<<dim3(DIM / 128, M / 128), 256, HGEMM_SMEM>>>(AOh, Woh, out);
}

// round 12
// speedup vs baseline: 1.0701x; 1.0701x over previous
#include <cuda_runtime.h>
#include <cuda_fp16.h>
#include <math.h>
#include <stdint.h>

#define BATCH 2
#define SEQ   2048
#define DIM   2048
#define KVDIM 512
#define NH    16
#define NKV   4
#define HD    128

// Scratch (__device__ globals: allocation-free rule)
__device__ __half g_Xh[BATCH * SEQ * DIM];
__device__ __half g_Wqh[DIM * DIM];
__device__ __half g_Wkh[KVDIM * DIM];
__device__ __half g_Wvh[KVDIM * DIM];
__device__ __half g_Woh[DIM * DIM];
__device__ __half g_Qh[BATCH * SEQ * DIM];
__device__ __half g_Kh[BATCH * SEQ * KVDIM];
__device__ __half g_Vh[BATCH * SEQ * KVDIM];
__device__ __half g_AOh[BATCH * SEQ * DIM];

__device__ __forceinline__ uint32_t h2u(__half2 h) {
    uint32_t u;
    memcpy(&u, &h, 4);
    return u;
}

__device__ __forceinline__ uint32_t smem_u32(const void* p) {
    return (uint32_t)__cvta_generic_to_shared(p);
}

__device__ __forceinline__ void mma16(float* d, const uint32_t* a, const uint32_t* b) {
    asm volatile(
        "mma.sync.aligned.m16n8k16.row.col.f32.f16.f16.f32 "
        "{%0,%1,%2,%3}, {%4,%5,%6,%7}, {%8,%9}, {%0,%1,%2,%3};"
        : "+f"(d[0]), "+f"(d[1]), "+f"(d[2]), "+f"(d[3])
        : "r"(a[0]), "r"(a[1]), "r"(a[2]), "r"(a[3]), "r"(b[0]), "r"(b[1]));
}

__device__ __forceinline__ void ldsm4(uint32_t* r, uint32_t saddr) {
    asm volatile(
        "ldmatrix.sync.aligned.m8n8.x4.shared.b16 {%0,%1,%2,%3}, [%4];"
        : "=r"(r[0]), "=r"(r[1]), "=r"(r[2]), "=r"(r[3]) : "r"(saddr));
}
__device__ __forceinline__ void ldsm4t(uint32_t* r, uint32_t saddr) {
    asm volatile(
        "ldmatrix.sync.aligned.m8n8.x4.trans.shared.b16 {%0,%1,%2,%3}, [%4];"
        : "=r"(r[0]), "=r"(r[1]), "=r"(r[2]), "=r"(r[3]) : "r"(saddr));
}

__device__ __forceinline__ void cp16(void* smem_dst, const void* gmem_src) {
    uint32_t sa = (uint32_t)__cvta_generic_to_shared(smem_dst);
    asm volatile("cp.async.cg.shared.global [%0], [%1], 16;\n" ::"r"(sa), "l"(gmem_src));
}
#define CP_COMMIT() asm volatile("cp.async.commit_group;\n" ::)
#define CP_WAIT(N) asm volatile("cp.async.wait_group %0;\n" ::"n"(N))

// ---------------------------------------------------------------------------
// One flattened launch converting all 5 fp32 tensors to fp16 (no idle blocks)
// ---------------------------------------------------------------------------
__global__ void to_half_all(const float2* s0, __half2* d0, int n0,
                            const float2* s1, __half2* d1, int n1,
                            const float2* s2, __half2* d2, int n2,
                            const float2* s3, __half2* d3, int n3,
                            const float2* s4, __half2* d4, int n4) {
    int i = blockIdx.x * blockDim.x + threadIdx.x;
    if (i < n0) { float2 v = s0[i]; d0[i] = __floats2half2_rn(v.x, v.y); return; }
    i -= n0;
    if (i < n1) { float2 v = s1[i]; d1[i] = __floats2half2_rn(v.x, v.y); return; }
    i -= n1;
    if (i < n2) { float2 v = s2[i]; d2[i] = __floats2half2_rn(v.x, v.y); return; }
    i -= n2;
    if (i < n3) { float2 v = s3[i]; d3[i] = __floats2half2_rn(v.x, v.y); return; }
    i -= n3;
    if (i < n4) { float2 v = s4[i]; d4[i] = __floats2half2_rn(v.x, v.y); }
}

// ---------------------------------------------------------------------------
// Shared GEMM body (fp16 mma + ldmatrix, 3-stage cp.async).
// Block 128x128, 8 warps (2Mx4N), warp 64x32, BK=32h.
// ---------------------------------------------------------------------------
#define HSTR2 20
#define HSTAGES 3
#define HSTAGE_U32 (128 * HSTR2)
#define HGEMM_SMEM (HSTAGES * 2 * HSTAGE_U32 * 4)  // 61440 B

template <bool HALF_OUT>
__device__ __forceinline__ void gemm_body(const __half* __restrict__ A,
                                          const __half* __restrict__ B,
                                          void* __restrict__ Cv, int N, int K,
                                          int mBase, int nBase, uint32_t* smp) {
    const uint32_t smb = smem_u32(smp);
    const int tid = threadIdx.x;
    const int lane = tid & 31;
    const int warp = tid >> 5;
    const int wm = warp >> 2;
    const int wn = warp & 3;
    const int gr = lane >> 2, tc = lane & 3;

    const int mat = lane >> 3;
    const int arow = (lane & 7) + ((mat & 1) << 3);
    const int acol = (mat >> 1) << 3;
    const int brow = (lane & 7) + ((mat >> 1) << 3);
    const int bcol = (mat & 1) << 3;

    float acc[4][4][4];
#pragma unroll
    for (int i = 0; i < 4; i++)
#pragma unroll
        for (int j = 0; j < 4; j++)
#pragma unroll
            for (int r = 0; r < 4; r++) acc[i][j][r] = 0.f;

    const int nK = K / 32;

#define GSTAGE(kt, s)                                                          \
    do {                                                                       \
        _Pragma("unroll") for (int i = 0; i < 2; i++) {                        \
            int c = tid + i * 256;                                             \
            int r = c >> 2, ch = c & 3;                                        \
            cp16(&smp[((s)*128 + r) * HSTR2 + ch * 4],                         \
                 A + (size_t)(mBase + r) * K + (kt)*32 + ch * 8);              \
            cp16(&smp[(HSTAGES * 128 + (s)*128 + r) * HSTR2 + ch * 4],         \
                 B + (size_t)(nBase + r) * K + (kt)*32 + ch * 8);              \
        }                                                                      \
    } while (0)

    GSTAGE(0, 0);
    CP_COMMIT();
    GSTAGE(1, 1);
    CP_COMMIT();

    for (int kt = 0; kt < nK; kt++) {
        CP_WAIT(1);
        __syncthreads();
        int nxt = kt + 2;
        if (nxt < nK) GSTAGE(nxt, nxt % HSTAGES);
        CP_COMMIT();

        const uint32_t Aoff = smb + (uint32_t)(kt % HSTAGES) * (HSTAGE_U32 * 4);
        const uint32_t Boff = Aoff + HSTAGES * (HSTAGE_U32 * 4);
#pragma unroll
        for (int ks = 0; ks < 2; ks++) {
            const int k0h = ks * 16;
            uint32_t af[4][4], bf0[4], bf1[4];
#pragma unroll
            for (int mt = 0; mt < 4; mt++)
                ldsm4(af[mt], Aoff + (wm * 64 + mt * 16 + arow) * 80 +
                                  (k0h + acol) * 2);
            ldsm4(bf0, Boff + (wn * 32 + brow) * 80 + (k0h + bcol) * 2);
            ldsm4(bf1, Boff + (wn * 32 + 16 + brow) * 80 + (k0h + bcol) * 2);
#pragma unroll
            for (int mt = 0; mt < 4; mt++) {
                mma16(acc[mt][0], af[mt], bf0 + 0);
                mma16(acc[mt][1], af[mt], bf0 + 2);
                mma16(acc[mt][2], af[mt], bf1 + 0);
                mma16(acc[mt][3], af[mt], bf1 + 2);
            }
        }
        __syncthreads();
    }
#undef GSTAGE

#pragma unroll
    for (int mt = 0; mt < 4; mt++) {
        int m0 = mBase + wm * 64 + mt * 16;
#pragma unroll
        for (int nt = 0; nt < 4; nt++) {
            int n0 = nBase + wn * 32 + nt * 8 + 2 * tc;
            if (HALF_OUT) {
                __half2* cp = (__half2*)((__half*)Cv + (size_t)(m0 + gr) * N + n0);
                __half2* cp2 = (__half2*)((__half*)Cv + (size_t)(m0 + gr + 8) * N + n0);
                *cp = __floats2half2_rn(acc[mt][nt][0], acc[mt][nt][1]);
                *cp2 = __floats2half2_rn(acc[mt][nt][2], acc[mt][nt][3]);
            } else {
                float* cp = (float*)Cv + (size_t)(m0 + gr) * N + n0;
                float* cp2 = (float*)Cv + (size_t)(m0 + gr + 8) * N + n0;
                cp[0] = acc[mt][nt][0];
                cp[1] = acc[mt][nt][1];
                cp2[0] = acc[mt][nt][2];
                cp2[1] = acc[mt][nt][3];
            }
        }
    }
}

// Merged Q/K/V projection: grid.x = 24 n-blocks (16 Q | 4 K | 4 V), grid.y = M/128
__global__ __launch_bounds__(256, 2) void gemm_qkv(const __half* __restrict__ Xh,
                                                   const __half* __restrict__ Wq,
                                                   __half* __restrict__ Qd,
                                                   const __half* __restrict__ Wk,
                                                   __half* __restrict__ Kd,
                                                   const __half* __restrict__ Wv,
                                                   __half* __restrict__ Vd) {
    extern __shared__ uint32_t smp[];
    const int bx = blockIdx.x;
    const __half* B;
    __half* C;
    int N, nb;
    if (bx < 16) {
        B = Wq; C = Qd; N = DIM; nb = bx;
    } else if (bx < 20) {
        B = Wk; C = Kd; N = KVDIM; nb = bx - 16;
    } else {
        B = Wv; C = Vd; N = KVDIM; nb = bx - 20;
    }
    gemm_body<true>(Xh, B, C, N, DIM, blockIdx.y * 128, nb * 128, smp);
}

// O projection (fp32 out)
__global__ __launch_bounds__(256, 2) void gemm_o(const __half* __restrict__ A,
                                                 const __half* __restrict__ B,
                                                 float* __restrict__ C) {
    extern __shared__ uint32_t smp[];
    gemm_body<false>(A, B, C, DIM, DIM, blockIdx.y * 128, blockIdx.x * 128, smp);
}

// ---------------------------------------------------------------------------
// Merged RoPE for Q and K (flattened index; Q gets 1/sqrt(128)*log2e folded)
// ---------------------------------------------------------------------------
__global__ void rope_both(__half* __restrict__ Qd, __half* __restrict__ Kd,
                          int qCount, float qscale) {
    int idx = blockIdx.x * blockDim.x + threadIdx.x;
    __half* X;
    int nCols, nHeads;
    float scale;
    if (idx < qCount) {
        X = Qd; nCols = DIM; nHeads = NH; scale = qscale;
    } else {
        idx -= qCount;
        X = Kd; nCols = KVDIM; nHeads = NKV; scale = 1.0f;
    }
    int i = idx & 63;
    int h = (idx >> 6) % nHeads;
    int row = idx / (64 * nHeads);
    int l = row & (SEQ - 1);

    float freq = expf(-(float)i * 0.14391156831212787f);
    float ang = (float)l * freq;
    float s, c;
    sincosf(ang, &s, &c);

    __half* p = X + (size_t)row * nCols + h * HD + i;
    float x1 = __half2float(p[0]);
    float x2 = __half2float(p[64]);
    p[0] = __float2half_rn((x1 * c - x2 * s) * scale);
    p[64] = __float2half_rn((x2 * c + x1 * s) * scale);
}

// ---------------------------------------------------------------------------
// Flash attention, fp16 mma + ldmatrix, cp.async pipelined, exp2 softmax.
// Q-tile pairing (i, 15-i): uniform 17 unit-tiles; 256 CTAs.
// __launch_bounds__(256,2): cap 128 regs -> 2 CTAs/SM -> single wave.
// smem: Qs[128][68], Ks[2][64][68], Vs[64][68] (b32 strides) = 87040 B.
// ---------------------------------------------------------------------------
#define AQS2 68
#define ATTN_SMEM ((128 * AQS2 + 2 * 64 * AQS2 + 64 * AQS2) * 4)

__global__ __launch_bounds__(256, 2) void attn_h(const __half* __restrict__ Q,
                                                 const __half* __restrict__ K,
                                                 const __half* __restrict__ V,
                                                 __half* __restrict__ O) {
    extern __shared__ uint32_t sm[];
    uint32_t* Qs = sm;                       // [128][68] b32
    uint32_t* Ks = Qs + 128 * AQS2;          // [2][64][68]
    uint32_t* Vs = Ks + 2 * 64 * AQS2;       // [64][68]

    const uint32_t Qaddr = smem_u32(Qs);
    const uint32_t Kaddr0 = smem_u32(Ks);
    const uint32_t Vaddr = smem_u32(Vs);

    const int tid = threadIdx.x, lane = tid & 31, warp = tid >> 5;
    const int gr = lane >> 2, tc = lane & 3;
    const int h = blockIdx.y, b = blockIdx.z;
    const int kh = h >> 2;
    const int nqt = gridDim.x * 2;  // 16 q-tiles total

    const int mat = lane >> 3;
    const int arow = (lane & 7) + ((mat & 1) << 3);
    const int acol = (mat >> 1) << 3;
    const int brow = (lane & 7) + ((mat >> 1) << 3);
    const int bcol = (mat & 1) << 3;

    const __half* Kbase = K + ((size_t)(b * SEQ)) * KVDIM + kh * HD;
    const __half* Vbase = V + ((size_t)(b * SEQ)) * KVDIM + kh * HD;
    const int q0 = warp * 16;

    for (int halfIdx = 0; halfIdx < 2; halfIdx++) {
        const int qTile = halfIdx ? (nqt - 1 - (int)blockIdx.x) : (int)blockIdx.x;
        const int qBase = qTile * 128;
        const __half* Qp = Q + ((size_t)(b * SEQ + qBase)) * DIM + h * HD;

        __syncthreads();

        // Prologue: stage Q + K(0)
        {
#pragma unroll
            for (int i = 0; i < 8; i++) {
                int c = tid + i * 256;
                int q = c >> 4;
                int ch = c & 15;
                cp16((char*)Qs + q * (AQS2 * 4) + ch * 16,
                     Qp + (size_t)q * DIM + ch * 8);
            }
#pragma unroll
            for (int i = 0; i < 4; i++) {
                int c = tid + i * 256;
                int key = c >> 4;
                int ch = c & 15;
                cp16((char*)Ks + key * (AQS2 * 4) + ch * 16,
                     Kbase + (size_t)key * KVDIM + ch * 8);
            }
            CP_COMMIT();
        }

        float m0r = -1e30f, m1r = -1e30f, l0 = 0.f, l1 = 0.f;
        float o[16][4];
#pragma unroll
        for (int i = 0; i < 16; i++)
#pragma unroll
            for (int j = 0; j < 4; j++) o[i][j] = 0.f;

        const int nT = 2 * qTile + 2;

        for (int t = 0; t < nT; t++) {
            const int buf = t & 1;
            CP_WAIT(0);
            __syncthreads();

            // Issue V(t)
            {
                const __half* Vp = Vbase + (size_t)(t * 64) * KVDIM;
#pragma unroll
                for (int i = 0; i < 4; i++) {
                    int c = tid + i * 256;
                    int key = c >> 4;
                    int ch = c & 15;
                    cp16((char*)Vs + key * (AQS2 * 4) + ch * 16,
                         Vp + (size_t)key * KVDIM + ch * 8);
                }
            }
            CP_COMMIT();
            // Issue K(t+1)
            if (t + 1 < nT) {
                const __half* Kp = Kbase + (size_t)((t + 1) * 64) * KVDIM;
                uint32_t* Kd = Ks + ((t + 1) & 1) * 64 * AQS2;
#pragma unroll
                for (int i = 0; i < 4; i++) {
                    int c = tid + i * 256;
                    int key = c >> 4;
                    int ch = c & 15;
                    cp16((char*)Kd + key * (AQS2 * 4) + ch * 16,
                         Kp + (size_t)key * KVDIM + ch * 8);
                }
            }
            CP_COMMIT();

            // S = Q*K^T (log2 domain)
            const uint32_t Kaddr = Kaddr0 + (uint32_t)buf * (64 * AQS2 * 4);
            float s[8][4];
#pragma unroll
            for (int nt = 0; nt < 8; nt++)
#pragma unroll
                for (int r = 0; r < 4; r++) s[nt][r] = 0.f;

#pragma unroll
            for (int dk = 0; dk < 8; dk++) {
                const int d0h = dk * 16;
                uint32_t aq[4];
                ldsm4(aq, Qaddr + (q0 + arow) * (AQS2 * 4) + (d0h + acol) * 2);
#pragma unroll
                for (int p = 0; p < 4; p++) {
                    uint32_t bk[4];
                    ldsm4(bk, Kaddr + (p * 16 + brow) * (AQS2 * 4) + (d0h + bcol) * 2);
                    mma16(s[2 * p], aq, bk + 0);
                    mma16(s[2 * p + 1], aq, bk + 2);
                }
            }

            // Causal mask
            if (t * 64 >= qBase) {
                int qrow = qBase + q0 + gr;
                int kcol = t * 64 + 2 * tc;
#pragma unroll
                for (int nt = 0; nt < 8; nt++) {
                    int kc = kcol + nt * 8;
                    if (kc > qrow) s[nt][0] = -1e30f;
                    if (kc + 1 > qrow) s[nt][1] = -1e30f;
                    if (kc > qrow + 8) s[nt][2] = -1e30f;
                    if (kc + 1 > qrow + 8) s[nt][3] = -1e30f;
                }
            }

            // Online softmax (exp2 domain)
            float rm0 = -1e30f, rm1 = -1e30f;
#pragma unroll
            for (int nt = 0; nt < 8; nt++) {
                rm0 = fmaxf(rm0, fmaxf(s[nt][0], s[nt][1]));
                rm1 = fmaxf(rm1, fmaxf(s[nt][2], s[nt][3]));
            }
            rm0 = fmaxf(rm0, __shfl_xor_sync(0xffffffffu, rm0, 1));
            rm0 = fmaxf(rm0, __shfl_xor_sync(0xffffffffu, rm0, 2));
            rm1 = fmaxf(rm1, __shfl_xor_sync(0xffffffffu, rm1, 1));
            rm1 = fmaxf(rm1, __shfl_xor_sync(0xffffffffu, rm1, 2));

            float mn0 = fmaxf(m0r, rm0), mn1 = fmaxf(m1r, rm1);
            float a0 = exp2f(m0r - mn0), a1 = exp2f(m1r - mn1);
            m0r = mn0;
            m1r = mn1;

            float rs0 = 0.f, rs1 = 0.f;
#pragma unroll
            for (int nt = 0; nt < 8; nt++) {
                s[nt][0] = exp2f(s[nt][0] - mn0);
                s[nt][1] = exp2f(s[nt][1] - mn0);
                s[nt][2] = exp2f(s[nt][2] - mn1);
                s[nt][3] = exp2f(s[nt][3] - mn1);
                rs0 += s[nt][0] + s[nt][1];
                rs1 += s[nt][2] + s[nt][3];
            }
            rs0 += __shfl_xor_sync(0xffffffffu, rs0, 1);
            rs0 += __shfl_xor_sync(0xffffffffu, rs0, 2);
            rs1 += __shfl_xor_sync(0xffffffffu, rs1, 1);
            rs1 += __shfl_xor_sync(0xffffffffu, rs1, 2);
            l0 = l0 * a0 + rs0;
            l1 = l1 * a1 + rs1;

#pragma unroll
            for (int ot = 0; ot < 16; ot++) {
                o[ot][0] *= a0;
                o[ot][1] *= a0;
                o[ot][2] *= a1;
                o[ot][3] *= a1;
            }

            // P fragments directly from S registers (C-frag == A-frag layout)
            uint32_t pf[4][4];
#pragma unroll
            for (int kk = 0; kk < 4; kk++) {
                pf[kk][0] = h2u(__floats2half2_rn(s[2 * kk][0], s[2 * kk][1]));
                pf[kk][1] = h2u(__floats2half2_rn(s[2 * kk][2], s[2 * kk][3]));
                pf[kk][2] = h2u(__floats2half2_rn(s[2 * kk + 1][0], s[2 * kk + 1][1]));
                pf[kk][3] = h2u(__floats2half2_rn(s[2 * kk + 1][2], s[2 * kk + 1][3]));
            }

            // V(t) must have landed (K(t+1) group still in flight)
            CP_WAIT(1);
            __syncthreads();

            // O += P * V : V frags via ldmatrix.trans
#pragma unroll
            for (int kk = 0; kk < 4; kk++) {
                const int k0h = kk * 16;
#pragma unroll
                for (int dp = 0; dp < 8; dp++) {
                    uint32_t bv[4];
                    ldsm4t(bv, Vaddr + (k0h + arow) * (AQS2 * 4) +
                                   (dp * 16 + acol) * 2);
                    mma16(o[2 * dp], pf[kk], bv + 0);
                    mma16(o[2 * dp + 1], pf[kk], bv + 2);
                }
            }
        }

        // Normalize + write half (feeds O-projection GEMM)
        float inv0 = 1.f / l0, inv1 = 1.f / l1;
        __half* Op = O + ((size_t)(b * SEQ + qBase + q0)) * DIM + h * HD;
#pragma unroll
        for (int ot = 0; ot < 16; ot++) {
            int d0 = ot * 8 + 2 * tc;
            *(__half2*)(Op + (size_t)gr * DIM + d0) =
                __floats2half2_rn(o[ot][0] * inv0, o[ot][1] * inv0);
            *(__half2*)(Op + (size_t)(gr + 8) * DIM + d0) =
                __floats2half2_rn(o[ot][2] * inv1, o[ot][3] * inv1);
        }
    }
}

// ---------------------------------------------------------------------------
extern "C" void kernel_launch(void* const* d_in, const int* in_sizes, int n_in,
                              void* d_out, int out_size) {
    const float* x = (const float*)d_in[0];
    const float* Wq = (const float*)d_in[1];
    const float* Wk = (const float*)d_in[2];
    const float* Wv = (const float*)d_in[3];
    const float* Wo = (const float*)d_in[4];
    float* out = (float*)d_out;

    __half *Xh, *Wqh, *Wkh, *Wvh, *Woh, *Qh, *Kh, *Vh, *AOh;
    cudaGetSymbolAddress((void**)&Xh, g_Xh);
    cudaGetSymbolAddress((void**)&Wqh, g_Wqh);
    cudaGetSymbolAddress((void**)&Wkh, g_Wkh);
    cudaGetSymbolAddress((void**)&Wvh, g_Wvh);
    cudaGetSymbolAddress((void**)&Woh, g_Woh);
    cudaGetSymbolAddress((void**)&Qh, g_Qh);
    cudaGetSymbolAddress((void**)&Kh, g_Kh);
    cudaGetSymbolAddress((void**)&Vh, g_Vh);
    cudaGetSymbolAddress((void**)&AOh, g_AOh);

    const int M = BATCH * SEQ;  // 4096

    // Single flattened conversion launch
    {
        int n0 = M * DIM / 2;
        int n1 = DIM * DIM / 2;
        int n2 = KVDIM * DIM / 2;
        int n3 = KVDIM * DIM / 2;
        int n4 = DIM * DIM / 2;
        int total = n0 + n1 + n2 + n3 + n4;
        to_half_all<<<(total + 255) / 256, 256>>>(
            (const float2*)x, (__half2*)Xh, n0, (const float2*)Wq, (__half2*)Wqh,
            n1, (const float2*)Wk, (__half2*)Wkh, n2, (const float2*)Wv,
            (__half2*)Wvh, n3, (const float2*)Wo, (__half2*)Woh, n4);
    }

    cudaFuncSetAttribute(gemm_qkv, cudaFuncAttributeMaxDynamicSharedMemorySize,
                         HGEMM_SMEM);
    cudaFuncSetAttribute(gemm_o, cudaFuncAttributeMaxDynamicSharedMemorySize,
                         HGEMM_SMEM);

    // Q, K, V projections in one launch: 24 n-blocks x 32 m-blocks
    gemm_qkv<<<dim3(24, M / 128), 256, HGEMM_SMEM>>>(Xh, Wqh, Qh, Wkh, Kh, Wvh, Vh);

    // Merged RoPE (Q scale folds 1/sqrt(128)*log2e for exp2 softmax)
    {
        const float qscale = 0.08838834764831845f * 1.4426950408889634f;
        int qCount = BATCH * SEQ * NH * 64;
        int kCount = BATCH * SEQ * NKV * 64;
        rope_both<<<(qCount + kCount + 255) / 256, 256>>>(Qh, Kh, qCount, qscale);
    }

    cudaFuncSetAttribute(attn_h, cudaFuncAttributeMaxDynamicSharedMemorySize,
                         ATTN_SMEM);
    attn_h<<<dim3(SEQ / 256, NH, BATCH), 256, ATTN_SMEM>>>(Qh, Kh, Vh, AOh);

    gemm_o<<<dim3(DIM / 128, M / 128), 256, HGEMM_SMEM>>>(AOh, Woh, out);
}

// round 13
// speedup vs baseline: 1.1498x; 1.0745x over previous
#include <cuda_runtime.h>
#include <cuda_fp16.h>
#include <math.h>
#include <stdint.h>

#define BATCH 2
#define SEQ   2048
#define DIM   2048
#define KVDIM 512
#define NH    16
#define NKV   4
#define HD    128

// Scratch (__device__ globals: allocation-free rule)
__device__ __half g_Xh[BATCH * SEQ * DIM];
__device__ __half g_Wqh[DIM * DIM];
__device__ __half g_Wkh[KVDIM * DIM];
__device__ __half g_Wvh[KVDIM * DIM];
__device__ __half g_Woh[DIM * DIM];
__device__ __half g_Qh[BATCH * SEQ * DIM];
__device__ __half g_Kh[BATCH * SEQ * KVDIM];
__device__ __half g_Vh[BATCH * SEQ * KVDIM];
__device__ __half g_AOh[BATCH * SEQ * DIM];

__device__ __forceinline__ uint32_t h2u(__half2 h) {
    uint32_t u;
    memcpy(&u, &h, 4);
    return u;
}

__device__ __forceinline__ uint32_t smem_u32(const void* p) {
    return (uint32_t)__cvta_generic_to_shared(p);
}

__device__ __forceinline__ void mma16(float* d, const uint32_t* a, const uint32_t* b) {
    asm volatile(
        "mma.sync.aligned.m16n8k16.row.col.f32.f16.f16.f32 "
        "{%0,%1,%2,%3}, {%4,%5,%6,%7}, {%8,%9}, {%0,%1,%2,%3};"
        : "+f"(d[0]), "+f"(d[1]), "+f"(d[2]), "+f"(d[3])
        : "r"(a[0]), "r"(a[1]), "r"(a[2]), "r"(a[3]), "r"(b[0]), "r"(b[1]));
}

__device__ __forceinline__ void ldsm4(uint32_t* r, uint32_t saddr) {
    asm volatile(
        "ldmatrix.sync.aligned.m8n8.x4.shared.b16 {%0,%1,%2,%3}, [%4];"
        : "=r"(r[0]), "=r"(r[1]), "=r"(r[2]), "=r"(r[3]) : "r"(saddr));
}
__device__ __forceinline__ void ldsm4t(uint32_t* r, uint32_t saddr) {
    asm volatile(
        "ldmatrix.sync.aligned.m8n8.x4.trans.shared.b16 {%0,%1,%2,%3}, [%4];"
        : "=r"(r[0]), "=r"(r[1]), "=r"(r[2]), "=r"(r[3]) : "r"(saddr));
}

__device__ __forceinline__ void cp16(void* smem_dst, const void* gmem_src) {
    uint32_t sa = (uint32_t)__cvta_generic_to_shared(smem_dst);
    asm volatile("cp.async.cg.shared.global [%0], [%1], 16;\n" ::"r"(sa), "l"(gmem_src));
}
#define CP_COMMIT() asm volatile("cp.async.commit_group;\n" ::)
#define CP_WAIT(N) asm volatile("cp.async.wait_group %0;\n" ::"n"(N))

// ---------------------------------------------------------------------------
// One flattened launch converting all 5 fp32 tensors to fp16 (no idle blocks)
// ---------------------------------------------------------------------------
__global__ void to_half_all(const float2* s0, __half2* d0, int n0,
                            const float2* s1, __half2* d1, int n1,
                            const float2* s2, __half2* d2, int n2,
                            const float2* s3, __half2* d3, int n3,
                            const float2* s4, __half2* d4, int n4) {
    int i = blockIdx.x * blockDim.x + threadIdx.x;
    if (i < n0) { float2 v = s0[i]; d0[i] = __floats2half2_rn(v.x, v.y); return; }
    i -= n0;
    if (i < n1) { float2 v = s1[i]; d1[i] = __floats2half2_rn(v.x, v.y); return; }
    i -= n1;
    if (i < n2) { float2 v = s2[i]; d2[i] = __floats2half2_rn(v.x, v.y); return; }
    i -= n2;
    if (i < n3) { float2 v = s3[i]; d3[i] = __floats2half2_rn(v.x, v.y); return; }
    i -= n3;
    if (i < n4) { float2 v = s4[i]; d4[i] = __floats2half2_rn(v.x, v.y); }
}

// ---------------------------------------------------------------------------
// Shared GEMM body (fp16 mma + ldmatrix, BK=64h double-buffered cp.async).
// Block 128x128, 8 warps (2Mx4N), warp 64x32.
// smem rows: 64 halves (128B) + 16B pad -> 144B stride, ldsm conflict-free.
// ---------------------------------------------------------------------------
#define HSTR2 36                      // words per row (144 B)
#define HSTAGES 2
#define HSTAGE_U32 (128 * HSTR2)      // per matrix per stage
#define HGEMM_SMEM (HSTAGES * 2 * HSTAGE_U32 * 4)  // 73728 B

template <bool HALF_OUT>
__device__ __forceinline__ void gemm_body(const __half* __restrict__ A,
                                          const __half* __restrict__ B,
                                          void* __restrict__ Cv, int N, int K,
                                          int mBase, int nBase, uint32_t* smp) {
    const uint32_t smb = smem_u32(smp);
    const int tid = threadIdx.x;
    const int lane = tid & 31;
    const int warp = tid >> 5;
    const int wm = warp >> 2;
    const int wn = warp & 3;
    const int gr = lane >> 2, tc = lane & 3;

    const int mat = lane >> 3;
    const int arow = (lane & 7) + ((mat & 1) << 3);
    const int acol = (mat >> 1) << 3;
    const int brow = (lane & 7) + ((mat >> 1) << 3);
    const int bcol = (mat & 1) << 3;

    float acc[4][4][4];
#pragma unroll
    for (int i = 0; i < 4; i++)
#pragma unroll
        for (int j = 0; j < 4; j++)
#pragma unroll
            for (int r = 0; r < 4; r++) acc[i][j][r] = 0.f;

    const int nK = K / 64;

    // stage k-tile kt into ring slot s: 128 rows x 8 chunks(16B) per matrix
#define GSTAGE(kt, s)                                                          \
    do {                                                                       \
        _Pragma("unroll") for (int i = 0; i < 4; i++) {                        \
            int c = tid + i * 256;                                             \
            int r = c >> 3, ch = c & 7;                                        \
            cp16(&smp[((s)*128 + r) * HSTR2 + ch * 4],                         \
                 A + (size_t)(mBase + r) * K + (kt)*64 + ch * 8);              \
            cp16(&smp[(HSTAGES * 128 + (s)*128 + r) * HSTR2 + ch * 4],         \
                 B + (size_t)(nBase + r) * K + (kt)*64 + ch * 8);              \
        }                                                                      \
    } while (0)

    GSTAGE(0, 0);
    CP_COMMIT();
    GSTAGE(1, 1);
    CP_COMMIT();

    for (int kt = 0; kt < nK; kt++) {
        CP_WAIT(1);
        __syncthreads();

        const uint32_t Aoff = smb + (uint32_t)(kt % HSTAGES) * (HSTAGE_U32 * 4);
        const uint32_t Boff = Aoff + HSTAGES * (HSTAGE_U32 * 4);
#pragma unroll
        for (int ks = 0; ks < 4; ks++) {
            const int k0h = ks * 16;
            uint32_t af[4][4], bf0[4], bf1[4];
#pragma unroll
            for (int mt = 0; mt < 4; mt++)
                ldsm4(af[mt], Aoff + (wm * 64 + mt * 16 + arow) * 144 +
                                  (k0h + acol) * 2);
            ldsm4(bf0, Boff + (wn * 32 + brow) * 144 + (k0h + bcol) * 2);
            ldsm4(bf1, Boff + (wn * 32 + 16 + brow) * 144 + (k0h + bcol) * 2);
#pragma unroll
            for (int mt = 0; mt < 4; mt++) {
                mma16(acc[mt][0], af[mt], bf0 + 0);
                mma16(acc[mt][1], af[mt], bf0 + 2);
                mma16(acc[mt][2], af[mt], bf1 + 0);
                mma16(acc[mt][3], af[mt], bf1 + 2);
            }
        }
        __syncthreads();
        int nxt = kt + 2;
        if (nxt < nK) {
            GSTAGE(nxt, nxt % HSTAGES);
            CP_COMMIT();
        } else {
            CP_COMMIT();  // keep group accounting uniform
        }
    }
#undef GSTAGE

#pragma unroll
    for (int mt = 0; mt < 4; mt++) {
        int m0 = mBase + wm * 64 + mt * 16;
#pragma unroll
        for (int nt = 0; nt < 4; nt++) {
            int n0 = nBase + wn * 32 + nt * 8 + 2 * tc;
            if (HALF_OUT) {
                __half2* cp = (__half2*)((__half*)Cv + (size_t)(m0 + gr) * N + n0);
                __half2* cp2 = (__half2*)((__half*)Cv + (size_t)(m0 + gr + 8) * N + n0);
                *cp = __floats2half2_rn(acc[mt][nt][0], acc[mt][nt][1]);
                *cp2 = __floats2half2_rn(acc[mt][nt][2], acc[mt][nt][3]);
            } else {
                float* cp = (float*)Cv + (size_t)(m0 + gr) * N + n0;
                float* cp2 = (float*)Cv + (size_t)(m0 + gr + 8) * N + n0;
                cp[0] = acc[mt][nt][0];
                cp[1] = acc[mt][nt][1];
                cp2[0] = acc[mt][nt][2];
                cp2[1] = acc[mt][nt][3];
            }
        }
    }
}

// Merged Q/K/V projection: grid.x = 24 n-blocks (16 Q | 4 K | 4 V), grid.y = M/128
__global__ __launch_bounds__(256, 2) void gemm_qkv(const __half* __restrict__ Xh,
                                                   const __half* __restrict__ Wq,
                                                   __half* __restrict__ Qd,
                                                   const __half* __restrict__ Wk,
                                                   __half* __restrict__ Kd,
                                                   const __half* __restrict__ Wv,
                                                   __half* __restrict__ Vd) {
    extern __shared__ uint32_t smp[];
    const int bx = blockIdx.x;
    const __half* B;
    __half* C;
    int N, nb;
    if (bx < 16) {
        B = Wq; C = Qd; N = DIM; nb = bx;
    } else if (bx < 20) {
        B = Wk; C = Kd; N = KVDIM; nb = bx - 16;
    } else {
        B = Wv; C = Vd; N = KVDIM; nb = bx - 20;
    }
    gemm_body<true>(Xh, B, C, N, DIM, blockIdx.y * 128, nb * 128, smp);
}

// O projection (fp32 out)
__global__ __launch_bounds__(256, 2) void gemm_o(const __half* __restrict__ A,
                                                 const __half* __restrict__ B,
                                                 float* __restrict__ C) {
    extern __shared__ uint32_t smp[];
    gemm_body<false>(A, B, C, DIM, DIM, blockIdx.y * 128, blockIdx.x * 128, smp);
}

// ---------------------------------------------------------------------------
// Merged RoPE for Q and K (flattened index; Q gets 1/sqrt(128)*log2e folded)
// ---------------------------------------------------------------------------
__global__ void rope_both(__half* __restrict__ Qd, __half* __restrict__ Kd,
                          int qCount, float qscale) {
    int idx = blockIdx.x * blockDim.x + threadIdx.x;
    __half* X;
    int nCols, nHeads;
    float scale;
    if (idx < qCount) {
        X = Qd; nCols = DIM; nHeads = NH; scale = qscale;
    } else {
        idx -= qCount;
        X = Kd; nCols = KVDIM; nHeads = NKV; scale = 1.0f;
    }
    int i = idx & 63;
    int h = (idx >> 6) % nHeads;
    int row = idx / (64 * nHeads);
    int l = row & (SEQ - 1);

    float freq = expf(-(float)i * 0.14391156831212787f);
    float ang = (float)l * freq;
    float s, c;
    sincosf(ang, &s, &c);

    __half* p = X + (size_t)row * nCols + h * HD + i;
    float x1 = __half2float(p[0]);
    float x2 = __half2float(p[64]);
    p[0] = __float2half_rn((x1 * c - x2 * s) * scale);
    p[64] = __float2half_rn((x2 * c + x1 * s) * scale);
}

// ---------------------------------------------------------------------------
// Flash attention, fp16 mma + ldmatrix, cp.async pipelined, exp2 softmax.
// Q-tile pairing (i, 15-i): uniform 17 unit-tiles; 256 CTAs.
// __launch_bounds__(256,2): cap 128 regs -> 2 CTAs/SM.
// smem: Qs[128][68], Ks[2][64][68], Vs[64][68] (b32 strides) = 87040 B.
// ---------------------------------------------------------------------------
#define AQS2 68
#define ATTN_SMEM ((128 * AQS2 + 2 * 64 * AQS2 + 64 * AQS2) * 4)

__global__ __launch_bounds__(256, 2) void attn_h(const __half* __restrict__ Q,
                                                 const __half* __restrict__ K,
                                                 const __half* __restrict__ V,
                                                 __half* __restrict__ O) {
    extern __shared__ uint32_t sm[];
    uint32_t* Qs = sm;                       // [128][68] b32
    uint32_t* Ks = Qs + 128 * AQS2;          // [2][64][68]
    uint32_t* Vs = Ks + 2 * 64 * AQS2;       // [64][68]

    const uint32_t Qaddr = smem_u32(Qs);
    const uint32_t Kaddr0 = smem_u32(Ks);
    const uint32_t Vaddr = smem_u32(Vs);

    const int tid = threadIdx.x, lane = tid & 31, warp = tid >> 5;
    const int gr = lane >> 2, tc = lane & 3;
    const int h = blockIdx.y, b = blockIdx.z;
    const int kh = h >> 2;
    const int nqt = gridDim.x * 2;  // 16 q-tiles total

    const int mat = lane >> 3;
    const int arow = (lane & 7) + ((mat & 1) << 3);
    const int acol = (mat >> 1) << 3;
    const int brow = (lane & 7) + ((mat >> 1) << 3);
    const int bcol = (mat & 1) << 3;

    const __half* Kbase = K + ((size_t)(b * SEQ)) * KVDIM + kh * HD;
    const __half* Vbase = V + ((size_t)(b * SEQ)) * KVDIM + kh * HD;
    const int q0 = warp * 16;

    for (int halfIdx = 0; halfIdx < 2; halfIdx++) {
        const int qTile = halfIdx ? (nqt - 1 - (int)blockIdx.x) : (int)blockIdx.x;
        const int qBase = qTile * 128;
        const __half* Qp = Q + ((size_t)(b * SEQ + qBase)) * DIM + h * HD;

        __syncthreads();

        // Prologue: stage Q + K(0)
        {
#pragma unroll
            for (int i = 0; i < 8; i++) {
                int c = tid + i * 256;
                int q = c >> 4;
                int ch = c & 15;
                cp16((char*)Qs + q * (AQS2 * 4) + ch * 16,
                     Qp + (size_t)q * DIM + ch * 8);
            }
#pragma unroll
            for (int i = 0; i < 4; i++) {
                int c = tid + i * 256;
                int key = c >> 4;
                int ch = c & 15;
                cp16((char*)Ks + key * (AQS2 * 4) + ch * 16,
                     Kbase + (size_t)key * KVDIM + ch * 8);
            }
            CP_COMMIT();
        }

        float m0r = -1e30f, m1r = -1e30f, l0 = 0.f, l1 = 0.f;
        float o[16][4];
#pragma unroll
        for (int i = 0; i < 16; i++)
#pragma unroll
            for (int j = 0; j < 4; j++) o[i][j] = 0.f;

        const int nT = 2 * qTile + 2;

        for (int t = 0; t < nT; t++) {
            const int buf = t & 1;
            CP_WAIT(0);
            __syncthreads();

            // Issue V(t)
            {
                const __half* Vp = Vbase + (size_t)(t * 64) * KVDIM;
#pragma unroll
                for (int i = 0; i < 4; i++) {
                    int c = tid + i * 256;
                    int key = c >> 4;
                    int ch = c & 15;
                    cp16((char*)Vs + key * (AQS2 * 4) + ch * 16,
                         Vp + (size_t)key * KVDIM + ch * 8);
                }
            }
            CP_COMMIT();
            // Issue K(t+1)
            if (t + 1 < nT) {
                const __half* Kp = Kbase + (size_t)((t + 1) * 64) * KVDIM;
                uint32_t* Kd = Ks + ((t + 1) & 1) * 64 * AQS2;
#pragma unroll
                for (int i = 0; i < 4; i++) {
                    int c = tid + i * 256;
                    int key = c >> 4;
                    int ch = c & 15;
                    cp16((char*)Kd + key * (AQS2 * 4) + ch * 16,
                         Kp + (size_t)key * KVDIM + ch * 8);
                }
            }
            CP_COMMIT();

            // S = Q*K^T (log2 domain)
            const uint32_t Kaddr = Kaddr0 + (uint32_t)buf * (64 * AQS2 * 4);
            float s[8][4];
#pragma unroll
            for (int nt = 0; nt < 8; nt++)
#pragma unroll
                for (int r = 0; r < 4; r++) s[nt][r] = 0.f;

#pragma unroll
            for (int dk = 0; dk < 8; dk++) {
                const int d0h = dk * 16;
                uint32_t aq[4];
                ldsm4(aq, Qaddr + (q0 + arow) * (AQS2 * 4) + (d0h + acol) * 2);
#pragma unroll
                for (int p = 0; p < 4; p++) {
                    uint32_t bk[4];
                    ldsm4(bk, Kaddr + (p * 16 + brow) * (AQS2 * 4) + (d0h + bcol) * 2);
                    mma16(s[2 * p], aq, bk + 0);
                    mma16(s[2 * p + 1], aq, bk + 2);
                }
            }

            // Causal mask
            if (t * 64 >= qBase) {
                int qrow = qBase + q0 + gr;
                int kcol = t * 64 + 2 * tc;
#pragma unroll
                for (int nt = 0; nt < 8; nt++) {
                    int kc = kcol + nt * 8;
                    if (kc > qrow) s[nt][0] = -1e30f;
                    if (kc + 1 > qrow) s[nt][1] = -1e30f;
                    if (kc > qrow + 8) s[nt][2] = -1e30f;
                    if (kc + 1 > qrow + 8) s[nt][3] = -1e30f;
                }
            }

            // Online softmax (exp2 domain)
            float rm0 = -1e30f, rm1 = -1e30f;
#pragma unroll
            for (int nt = 0; nt < 8; nt++) {
                rm0 = fmaxf(rm0, fmaxf(s[nt][0], s[nt][1]));
                rm1 = fmaxf(rm1, fmaxf(s[nt][2], s[nt][3]));
            }
            rm0 = fmaxf(rm0, __shfl_xor_sync(0xffffffffu, rm0, 1));
            rm0 = fmaxf(rm0, __shfl_xor_sync(0xffffffffu, rm0, 2));
            rm1 = fmaxf(rm1, __shfl_xor_sync(0xffffffffu, rm1, 1));
            rm1 = fmaxf(rm1, __shfl_xor_sync(0xffffffffu, rm1, 2));

            float mn0 = fmaxf(m0r, rm0), mn1 = fmaxf(m1r, rm1);
            float a0 = exp2f(m0r - mn0), a1 = exp2f(m1r - mn1);
            m0r = mn0;
            m1r = mn1;

            float rs0 = 0.f, rs1 = 0.f;
#pragma unroll
            for (int nt = 0; nt < 8; nt++) {
                s[nt][0] = exp2f(s[nt][0] - mn0);
                s[nt][1] = exp2f(s[nt][1] - mn0);
                s[nt][2] = exp2f(s[nt][2] - mn1);
                s[nt][3] = exp2f(s[nt][3] - mn1);
                rs0 += s[nt][0] + s[nt][1];
                rs1 += s[nt][2] + s[nt][3];
            }
            rs0 += __shfl_xor_sync(0xffffffffu, rs0, 1);
            rs0 += __shfl_xor_sync(0xffffffffu, rs0, 2);
            rs1 += __shfl_xor_sync(0xffffffffu, rs1, 1);
            rs1 += __shfl_xor_sync(0xffffffffu, rs1, 2);
            l0 = l0 * a0 + rs0;
            l1 = l1 * a1 + rs1;

#pragma unroll
            for (int ot = 0; ot < 16; ot++) {
                o[ot][0] *= a0;
                o[ot][1] *= a0;
                o[ot][2] *= a1;
                o[ot][3] *= a1;
            }

            // P fragments directly from S registers (C-frag == A-frag layout)
            uint32_t pf[4][4];
#pragma unroll
            for (int kk = 0; kk < 4; kk++) {
                pf[kk][0] = h2u(__floats2half2_rn(s[2 * kk][0], s[2 * kk][1]));
                pf[kk][1] = h2u(__floats2half2_rn(s[2 * kk][2], s[2 * kk][3]));
                pf[kk][2] = h2u(__floats2half2_rn(s[2 * kk + 1][0], s[2 * kk + 1][1]));
                pf[kk][3] = h2u(__floats2half2_rn(s[2 * kk + 1][2], s[2 * kk + 1][3]));
            }

            // V(t) must have landed (K(t+1) group still in flight)
            CP_WAIT(1);
            __syncthreads();

            // O += P * V : V frags via ldmatrix.trans
#pragma unroll
            for (int kk = 0; kk < 4; kk++) {
                const int k0h = kk * 16;
#pragma unroll
                for (int dp = 0; dp < 8; dp++) {
                    uint32_t bv[4];
                    ldsm4t(bv, Vaddr + (k0h + arow) * (AQS2 * 4) +
                                   (dp * 16 + acol) * 2);
                    mma16(o[2 * dp], pf[kk], bv + 0);
                    mma16(o[2 * dp + 1], pf[kk], bv + 2);
                }
            }
        }

        // Normalize + write half (feeds O-projection GEMM)
        float inv0 = 1.f / l0, inv1 = 1.f / l1;
        __half* Op = O + ((size_t)(b * SEQ + qBase + q0)) * DIM + h * HD;
#pragma unroll
        for (int ot = 0; ot < 16; ot++) {
            int d0 = ot * 8 + 2 * tc;
            *(__half2*)(Op + (size_t)gr * DIM + d0) =
                __floats2half2_rn(o[ot][0] * inv0, o[ot][1] * inv0);
            *(__half2*)(Op + (size_t)(gr + 8) * DIM + d0) =
                __floats2half2_rn(o[ot][2] * inv1, o[ot][3] * inv1);
        }
    }
}

// ---------------------------------------------------------------------------
extern "C" void kernel_launch(void* const* d_in, const int* in_sizes, int n_in,
                              void* d_out, int out_size) {
    const float* x = (const float*)d_in[0];
    const float* Wq = (const float*)d_in[1];
    const float* Wk = (const float*)d_in[2];
    const float* Wv = (const float*)d_in[3];
    const float* Wo = (const float*)d_in[4];
    float* out = (float*)d_out;

    __half *Xh, *Wqh, *Wkh, *Wvh, *Woh, *Qh, *Kh, *Vh, *AOh;
    cudaGetSymbolAddress((void**)&Xh, g_Xh);
    cudaGetSymbolAddress((void**)&Wqh, g_Wqh);
    cudaGetSymbolAddress((void**)&Wkh, g_Wkh);
    cudaGetSymbolAddress((void**)&Wvh, g_Wvh);
    cudaGetSymbolAddress((void**)&Woh, g_Woh);
    cudaGetSymbolAddress((void**)&Qh, g_Qh);
    cudaGetSymbolAddress((void**)&Kh, g_Kh);
    cudaGetSymbolAddress((void**)&Vh, g_Vh);
    cudaGetSymbolAddress((void**)&AOh, g_AOh);

    const int M = BATCH * SEQ;  // 4096

    // Single flattened conversion launch
    {
        int n0 = M * DIM / 2;
        int n1 = DIM * DIM / 2;
        int n2 = KVDIM * DIM / 2;
        int n3 = KVDIM * DIM / 2;
        int n4 = DIM * DIM / 2;
        int total = n0 + n1 + n2 + n3 + n4;
        to_half_all<<<(total + 255) / 256, 256>>>(
            (const float2*)x, (__half2*)Xh, n0, (const float2*)Wq, (__half2*)Wqh,
            n1, (const float2*)Wk, (__half2*)Wkh, n2, (const float2*)Wv,
            (__half2*)Wvh, n3, (const float2*)Wo, (__half2*)Woh, n4);
    }

    cudaFuncSetAttribute(gemm_qkv, cudaFuncAttributeMaxDynamicSharedMemorySize,
                         HGEMM_SMEM);
    cudaFuncSetAttribute(gemm_o, cudaFuncAttributeMaxDynamicSharedMemorySize,
                         HGEMM_SMEM);

    // Q, K, V projections in one launch: 24 n-blocks x 32 m-blocks
    gemm_qkv<<<dim3(24, M / 128), 256, HGEMM_SMEM>>>(Xh, Wqh, Qh, Wkh, Kh, Wvh, Vh);

    // Merged RoPE (Q scale folds 1/sqrt(128)*log2e for exp2 softmax)
    {
        const float qscale = 0.08838834764831845f * 1.4426950408889634f;
        int qCount = BATCH * SEQ * NH * 64;
        int kCount = BATCH * SEQ * NKV * 64;
        rope_both<<<(qCount + kCount + 255) / 256, 256>>>(Qh, Kh, qCount, qscale);
    }

    cudaFuncSetAttribute(attn_h, cudaFuncAttributeMaxDynamicSharedMemorySize,
                         ATTN_SMEM);
    attn_h<<<dim3(SEQ / 256, NH, BATCH), 256, ATTN_SMEM>>>(Qh, Kh, Vh, AOh);

    gemm_o<<<dim3(DIM / 128, M / 128), 256, HGEMM_SMEM>>>(AOh, Woh, out);
}